// round 10
// baseline (speedup 1.0000x reference)
#include <cuda_runtime.h>
#include <cstdint>

#define IN_DIM      8192
#define OUT_DIM     8192
#define NUM_GROUPS  64
#define BLOCK       256                 // 8 warps; each block computes ONE output row
#define NWARP       (BLOCK / 32)
#define NCHUNK      2
#define CHUNK_F4    1024                // float4 per 16 KB chunk
#define CHUNK_BYTES 16384
#define ITERS_PER_CHUNK (CHUNK_F4 / BLOCK)   // 4

__device__ __forceinline__ uint32_t smem_u32(const void* p) {
    uint32_t a;
    asm("{ .reg .u64 t; cvta.to.shared.u64 t, %1; cvt.u32.u64 %0, t; }"
        : "=r"(a) : "l"(p));
    return a;
}

__device__ __forceinline__ void mbar_wait_parity0(uint32_t mb) {
    // acquire try_wait loop, parity 0 (HW sleep, not spin-poll)
    while (true) {
        uint32_t done;
        asm volatile(
            "{\n\t.reg .pred p;\n\t"
            "mbarrier.try_wait.parity.acquire.cta.shared::cta.b64 p, [%1], %2, 0x989680;\n\t"
            "selp.b32 %0, 1, 0, p;\n\t}"
            : "=r"(done) : "r"(mb), "r"(0u) : "memory");
        if (done) break;
    }
}

__global__ __launch_bounds__(BLOCK) void gql_kernel(
    const float* __restrict__ x,
    const float* __restrict__ w,
    const float* __restrict__ scales,
    float* __restrict__ out)
{
    // W row staged by async bulk copies: 2 x 16 KB buffers
    __shared__ __align__(128) float4  wbuf[NCHUNK][CHUNK_F4];
    __shared__ __align__(8)   uint64_t mbar[NCHUNK];
    __shared__ float red[NWARP];

    const int tid  = threadIdx.x;
    const int row  = blockIdx.x;
    const int wid  = tid >> 5;
    const int lane = tid & 31;

    const uint32_t mb0 = smem_u32(&mbar[0]);

    if (tid == 0) {
        asm volatile("mbarrier.init.shared.b64 [%0], %1;" :: "r"(mb0),     "r"(1) : "memory");
        asm volatile("mbarrier.init.shared.b64 [%0], %1;" :: "r"(mb0 + 8), "r"(1) : "memory");
    }
    __syncthreads();

    // One thread issues BOTH 16 KB bulk copies up front: the whole 32 KB row
    // is in flight immediately, independent of register pressure / warp
    // scheduling. W bypasses L1 entirely (async proxy), so x stays L1-hot.
    if (tid == 0) {
        const char* src = (const char*)(w + (size_t)row * IN_DIM);
        #pragma unroll
        for (int c = 0; c < NCHUNK; ++c) {
            const uint32_t mb  = mb0 + c * 8;
            const uint32_t dst = smem_u32(&wbuf[c][0]);
            asm volatile("mbarrier.arrive.expect_tx.shared.b64 _, [%0], %1;"
                         :: "r"(mb), "r"(CHUNK_BYTES) : "memory");
            asm volatile(
                "cp.async.bulk.shared::cta.global.mbarrier::complete_tx::bytes "
                "[%0], [%1], %2, [%3];"
                :: "r"(dst), "l"(src + (size_t)c * CHUNK_BYTES),
                   "r"(CHUNK_BYTES), "r"(mb) : "memory");
        }
    }

    const float4* x4 = (const float4*)x;
    const float*  sr = scales + (size_t)row * NUM_GROUPS;

    float acc = 0.f;

    #pragma unroll
    for (int c = 0; c < NCHUNK; ++c) {
        mbar_wait_parity0(mb0 + c * 8);

        #pragma unroll
        for (int it = 0; it < ITERS_PER_CHUNK; ++it) {
            const int li  = it * BLOCK + tid;         // float4 index in chunk
            const int gi  = c * CHUNK_F4 + li;        // float4 index in row
            const float4 a  = wbuf[c][li];            // LDS.128, conflict-free
            const float4 xv = __ldg(&x4[gi]);         // L1-persistent across CTAs
            // group = (gi*4)/128 = gi>>5, warp-uniform:
            const float  s  = __ldg(&sr[c * 32 + it * NWARP + wid]);

            float d = fmaf(rintf(fminf(fmaxf(a.x, -8.f), 7.f)), xv.x,
                      fmaf(rintf(fminf(fmaxf(a.y, -8.f), 7.f)), xv.y,
                      fmaf(rintf(fminf(fmaxf(a.z, -8.f), 7.f)), xv.z,
                           rintf(fminf(fmaxf(a.w, -8.f), 7.f)) * xv.w)));
            acc = fmaf(s, d, acc);
        }
    }

    // Warp reduction
    #pragma unroll
    for (int o = 16; o; o >>= 1)
        acc += __shfl_xor_sync(0xffffffffu, acc, o);
    if (lane == 0) red[wid] = acc;
    __syncthreads();

    // First warp reduces the 8 warp partials
    if (tid < 32) {
        float v = (lane < NWARP) ? red[lane] : 0.f;
        v += __shfl_xor_sync(0xffffffffu, v, 4);
        v += __shfl_xor_sync(0xffffffffu, v, 2);
        v += __shfl_xor_sync(0xffffffffu, v, 1);
        if (lane == 0) out[row] = v;
    }
}

extern "C" void kernel_launch(void* const* d_in, const int* in_sizes, int n_in,
                              void* d_out, int out_size)
{
    // Resolve inputs by element count (robust to ordering):
    //   weights = 67108864, scales = 524288, x = 8192
    const float* x      = nullptr;
    const float* w      = nullptr;
    const float* scales = nullptr;
    for (int i = 0; i < n_in; ++i) {
        if      (in_sizes[i] == OUT_DIM * IN_DIM)     w      = (const float*)d_in[i];
        else if (in_sizes[i] == OUT_DIM * NUM_GROUPS) scales = (const float*)d_in[i];
        else if (in_sizes[i] == IN_DIM)               x      = (const float*)d_in[i];
    }
    if (!x)      x      = (const float*)d_in[0];
    if (!w)      w      = (const float*)d_in[1];
    if (!scales) scales = (const float*)d_in[2];

    float* out = (float*)d_out;
    gql_kernel<<<OUT_DIM, BLOCK>>>(x, w, scales, out);
}

// round 12
// speedup vs baseline: 1.0994x; 1.0994x over previous
#include <cuda_runtime.h>
#include <cuda_bf16.h>

#define IN_DIM     8192
#define OUT_DIM    8192
#define NUM_GROUPS 64
#define BLOCK      256        // 8 warps; each block computes ONE output row
#define NWARP      (BLOCK / 32)
#define ITERS      (IN_DIM / (4 * BLOCK))   // 8 float4 iterations per thread

// min 3 blocks/SM -> reg budget 85: lets the full 8-deep W batch live in regs
__global__ __launch_bounds__(BLOCK, 3) void gql_kernel(
    const float* __restrict__ x,
    const float* __restrict__ w,
    const float* __restrict__ scales,
    float* __restrict__ out)
{
    __shared__ float red[NWARP];

    const int tid  = threadIdx.x;
    const int row  = blockIdx.x;
    const int wid  = tid >> 5;
    const int lane = tid & 31;

    const float4* x4 = (const float4*)x;
    const float4* w4 = (const float4*)(w + (size_t)row * IN_DIM);
    const float*  sr = scales + (size_t)row * NUM_GROUPS;

    // Preload this thread's 8 group scales (L2 hits, batched, out of hot loop).
    // Scale for iteration it is warp-uniform: group = it*8 + wid.
    float s8[ITERS];
    #pragma unroll
    for (int it = 0; it < ITERS; ++it)
        s8[it] = __ldg(&sr[it * NWARP + wid]);

    // FORCE 8-deep MLP: issue all 8 W LDG.128 before any math touches them.
    // 32 regs of W in flight per thread -> 4 KB per warp -> ~96 KB per SM at
    // 24 resident warps, far above the ~16 KB latency-BW product. W is .cs
    // (evict-first) so the one-pass 256 MB stream never evicts x from L1.
    float4 wv[ITERS];
    #pragma unroll
    for (int it = 0; it < ITERS; ++it)
        wv[it] = __ldcs(&w4[it * BLOCK + tid]);

    float acc = 0.f;
    #pragma unroll
    for (int it = 0; it < ITERS; ++it) {
        const float4 xv = __ldg(&x4[it * BLOCK + tid]);   // L1-persistent x
        const float4 a  = wv[it];
        float d = fmaf(rintf(fminf(fmaxf(a.x, -8.f), 7.f)), xv.x,
                  fmaf(rintf(fminf(fmaxf(a.y, -8.f), 7.f)), xv.y,
                  fmaf(rintf(fminf(fmaxf(a.z, -8.f), 7.f)), xv.z,
                       rintf(fminf(fmaxf(a.w, -8.f), 7.f)) * xv.w)));
        acc = fmaf(s8[it], d, acc);
    }

    // Warp reduction
    #pragma unroll
    for (int o = 16; o; o >>= 1)
        acc += __shfl_xor_sync(0xffffffffu, acc, o);
    if (lane == 0) red[wid] = acc;
    __syncthreads();

    // First warp reduces the 8 warp partials
    if (tid < 32) {
        float v = (lane < NWARP) ? red[lane] : 0.f;
        v += __shfl_xor_sync(0xffffffffu, v, 4);
        v += __shfl_xor_sync(0xffffffffu, v, 2);
        v += __shfl_xor_sync(0xffffffffu, v, 1);
        if (lane == 0) out[row] = v;
    }
}

extern "C" void kernel_launch(void* const* d_in, const int* in_sizes, int n_in,
                              void* d_out, int out_size)
{
    // Resolve inputs by element count (robust to ordering):
    //   weights = 67108864, scales = 524288, x = 8192
    const float* x      = nullptr;
    const float* w      = nullptr;
    const float* scales = nullptr;
    for (int i = 0; i < n_in; ++i) {
        if      (in_sizes[i] == OUT_DIM * IN_DIM)     w      = (const float*)d_in[i];
        else if (in_sizes[i] == OUT_DIM * NUM_GROUPS) scales = (const float*)d_in[i];
        else if (in_sizes[i] == IN_DIM)               x      = (const float*)d_in[i];
    }
    if (!x)      x      = (const float*)d_in[0];
    if (!w)      w      = (const float*)d_in[1];
    if (!scales) scales = (const float*)d_in[2];

    float* out = (float*)d_out;
    gql_kernel<<<OUT_DIM, BLOCK>>>(x, w, scales, out);
}